// round 14
// baseline (speedup 1.0000x reference)
#include <cuda_runtime.h>
#include <cstdint>

// ---------------- constants (eV / Angstrom natural units) -------------------
#define CE        14.399645478425668f   // KQQ * e / 1e-10 (eV*A per e^2)
#define BETA_OVR0 8.5f                  // 18.7 / 2.2
#define BETA      18.7f
#define EW_P      0.3275911f
#define EW_A0     0.254829592f
#define EW_A1     (-0.284496736f)
#define EW_A2     1.421413741f
#define EW_A3     (-1.453152027f)
#define EW_A4     1.061405429f
#define EW_F      2.0f
#define A2M       1e-10f

#define N_ATOMS_MAX 200000
#define N_GRAPHS    256

// scratch: per-atom accumulator {fx, fy, fz, e_atom}  (3.2 MB, L2-resident).
// Invariant: all-zero at entry to every kernel_launch call. Zero-initialized
// at module load; finish_kernel restores zeros after consuming it, so the
// invariant holds across graph replays.
__device__ float4 g_f4[N_ATOMS_MAX];

// fire-and-forget 128-bit global reduction
__device__ __forceinline__ void red_add_f4(float4* p, float x, float y, float z, float w) {
    asm volatile("red.global.add.v4.f32 [%0], {%1, %2, %3, %4};"
                 :: "l"(p), "f"(x), "f"(y), "f"(z), "f"(w) : "memory");
}

// ---------------- per-edge compute + scatter ---------------------------------
__device__ __forceinline__ void do_edge(
    float dx, float dy, float dz, int r, int c,
    const float* __restrict__ q, float gA)
{
    float r2    = fmaf(dx, dx, fmaf(dy, dy, dz * dz));
    float inv_r = rsqrtf(r2);
    float rij   = r2 * inv_r;                       // Angstrom

    float pref = CE * __ldg(&q[r]) * __ldg(&q[c]) * inv_r;   // eV

    // branchless short-range damping: arg < 0 for rij < r0, clamped to 0 above
    float damp = __expf(fminf(fmaf(BETA_OVR0, rij, -BETA), 0.0f));

    // Ewald real-space correction (A&S erfc polynomial)
    float grij  = gA * rij;
    float expm2 = __expf(-grij * grij);
    float t     = 1.0f / fmaf(EW_P, grij, 1.0f);
    float erfc  = t * fmaf(t, fmaf(t, fmaf(t, fmaf(t, EW_A4, EW_A3), EW_A2), EW_A1), EW_A0) * expm2;

    float ecoul = pref * (fmaf(0.5f, damp, erfc) - 1.0f);                    // eV
    float fcoul = pref * (damp + erfc + EW_F * grij * expm2 - 1.0f) * inv_r; // eV/A

    float s  = fcoul * inv_r;
    float fx = dx * s;
    float fy = dy * s;
    float fz = dz * s;

    red_add_f4(&g_f4[r],  fx,  fy,  fz, ecoul);
    red_add_f4(&g_f4[c], -fx, -fy, -fz, 0.0f);
}

// -------------------- kernel 1: fused per-edge pass (4 edges/thread) --------
__global__ __launch_bounds__(64) void edge_kernel(
    const float4* __restrict__ dij4,      // [E*3/4]
    const float*  __restrict__ q,         // [N]
    const float*  __restrict__ g_ewald,   // [1] 1/m
    const int4*   __restrict__ row4,      // [E/4]
    const int4*   __restrict__ col4,      // [E/4]
    float*        __restrict__ out_energy,// [256] zeroed here (read only in finish)
    int n_chunks)
{
    // free zeroing of the energy output: nothing reads it until finish_kernel
    if (blockIdx.x < 4) {
        out_energy[blockIdx.x * 64 + threadIdx.x] = 0.0f;
    }

    const float gA = g_ewald[0] * A2M;    // 1/Angstrom
    int j = blockIdx.x * blockDim.x + threadIdx.x;
    if (j >= n_chunks) return;

    // streaming loads: evict-first so q table keeps L1/L2 residency
    int4 r = __ldcs(&row4[j]);
    int4 c = __ldcs(&col4[j]);
    float4 d0 = __ldcs(&dij4[3 * j + 0]);
    float4 d1 = __ldcs(&dij4[3 * j + 1]);
    float4 d2 = __ldcs(&dij4[3 * j + 2]);

    do_edge(d0.x, d0.y, d0.z, r.x, c.x, q, gA);
    do_edge(d0.w, d1.x, d1.y, r.y, c.y, q, gA);
    do_edge(d1.z, d1.w, d2.x, r.z, c.z, q, gA);
    do_edge(d2.y, d2.z, d2.w, r.w, c.w, q, gA);
}

// tail handler for n_edges not divisible by 4
__global__ void edge_tail_kernel(
    const float* __restrict__ dij,
    const float* __restrict__ q,
    const float* __restrict__ g_ewald,
    const int*   __restrict__ row,
    const int*   __restrict__ col,
    int e_start, int n_edges)
{
    int i = e_start + blockIdx.x * blockDim.x + threadIdx.x;
    if (i < n_edges) {
        const float gA = g_ewald[0] * A2M;
        do_edge(dij[3 * i], dij[3 * i + 1], dij[3 * i + 2], row[i], col[i], q, gA);
    }
}

// ------------- kernel 2: unpack force + bin energy + restore scratch --------
// (proven R8 form: 1 atom/thread, warp-uniform energy reduction)
__global__ __launch_bounds__(256) void finish_kernel(
    const int* __restrict__ batch,        // [N] atom -> graph (sorted)
    float*     __restrict__ out_energy,   // [256]
    float*     __restrict__ out_force,    // [N,3]
    int n_atoms)
{
    __shared__ float s_e[N_GRAPHS];
    s_e[threadIdx.x] = 0.0f;
    __syncthreads();

    int a = blockIdx.x * blockDim.x + threadIdx.x;
    if (a < n_atoms) {
        float4 f = g_f4[a];
        g_f4[a] = make_float4(0.f, 0.f, 0.f, 0.f);   // restore zero invariant
        out_force[3 * a + 0] = f.x;
        out_force[3 * a + 1] = f.y;
        out_force[3 * a + 2] = f.z;

        int b = batch[a];
        // batch is sorted -> most warps are uniform: reduce in registers,
        // single shared atomic per warp. Boundary warps take per-lane path.
        unsigned act = __activemask();
        int b0 = __shfl_sync(act, b, 0);
        if (act == 0xFFFFFFFFu && __all_sync(act, b == b0)) {
            float v = f.w;
            v += __shfl_down_sync(act, v, 16);
            v += __shfl_down_sync(act, v, 8);
            v += __shfl_down_sync(act, v, 4);
            v += __shfl_down_sync(act, v, 2);
            v += __shfl_down_sync(act, v, 1);
            if ((threadIdx.x & 31) == 0) atomicAdd(&s_e[b0], v);
        } else {
            atomicAdd(&s_e[b], f.w);
        }
    }
    __syncthreads();

    float v = s_e[threadIdx.x];
    if (v != 0.0f) atomicAdd(&out_energy[threadIdx.x], v);
}

// -----------------------------------------------------------------------------
extern "C" void kernel_launch(void* const* d_in, const int* in_sizes, int n_in,
                              void* d_out, int out_size)
{
    const float* dij     = (const float*)d_in[0];   // [E,3]
    const float* q       = (const float*)d_in[1];   // [N]
    const float* g_ewald = (const float*)d_in[2];   // [1]
    const int*   row     = (const int*)d_in[3];     // [E]
    const int*   col     = (const int*)d_in[4];     // [E]
    const int*   batch   = (const int*)d_in[5];     // [N]

    int n_edges = in_sizes[0] / 3;
    int n_atoms = in_sizes[1];

    float* out        = (float*)d_out;
    float* out_energy = out;                 // [256]
    float* out_force  = out + N_GRAPHS;      // [N,3]

    // one 4-edge chunk per thread; 64-thread CTAs for finest wave balancing
    int n_chunks = n_edges / 4;
    edge_kernel<<<(n_chunks + 63) / 64, 64>>>((const float4*)dij, q, g_ewald,
                                              (const int4*)row, (const int4*)col,
                                              out_energy, n_chunks);

    int tail = n_edges - n_chunks * 4;
    if (tail > 0) {
        edge_tail_kernel<<<1, 256>>>(dij, q, g_ewald, row, col,
                                     n_chunks * 4, n_edges);
    }

    // unpack + energy binning + scratch restore
    finish_kernel<<<(n_atoms + 255) / 256, 256>>>(batch, out_energy, out_force, n_atoms);
}

// round 15
// speedup vs baseline: 1.0019x; 1.0019x over previous
#include <cuda_runtime.h>
#include <cstdint>

// ---------------- constants (eV / Angstrom natural units) -------------------
#define CE        14.399645478425668f   // KQQ * e / 1e-10 (eV*A per e^2)
#define BETA_OVR0 8.5f                  // 18.7 / 2.2
#define BETA      18.7f
#define EW_P      0.3275911f
#define EW_A0     0.254829592f
#define EW_A1     (-0.284496736f)
#define EW_A2     1.421413741f
#define EW_A3     (-1.453152027f)
#define EW_A4     1.061405429f
#define EW_F      2.0f
#define A2M       1e-10f

#define N_ATOMS_MAX 200000
#define N_GRAPHS    256

// scratch: per-atom accumulator {fx, fy, fz, e_atom}  (3.2 MB, L2-resident).
// Invariant: all-zero at entry to every kernel_launch call. Zero-initialized
// at module load; finish_kernel restores zeros after consuming it, so the
// invariant holds across graph replays.
__device__ float4 g_f4[N_ATOMS_MAX];

// fire-and-forget 128-bit global reduction
__device__ __forceinline__ void red_add_f4(float4* p, float x, float y, float z, float w) {
    asm volatile("red.global.add.v4.f32 [%0], {%1, %2, %3, %4};"
                 :: "l"(p), "f"(x), "f"(y), "f"(z), "f"(w) : "memory");
}

// ---------------- per-edge compute + scatter ---------------------------------
__device__ __forceinline__ void do_edge(
    float dx, float dy, float dz, int r, int c,
    const float* __restrict__ q, float gA)
{
    float r2    = fmaf(dx, dx, fmaf(dy, dy, dz * dz));
    float inv_r = rsqrtf(r2);
    float rij   = r2 * inv_r;                       // Angstrom

    float pref = CE * __ldg(&q[r]) * __ldg(&q[c]) * inv_r;   // eV

    // branchless short-range damping: arg < 0 for rij < r0, clamped to 0 above
    float damp = __expf(fminf(fmaf(BETA_OVR0, rij, -BETA), 0.0f));

    // Ewald real-space correction (A&S erfc polynomial)
    float grij  = gA * rij;
    float expm2 = __expf(-grij * grij);
    float t     = 1.0f / fmaf(EW_P, grij, 1.0f);
    float erfc  = t * fmaf(t, fmaf(t, fmaf(t, fmaf(t, EW_A4, EW_A3), EW_A2), EW_A1), EW_A0) * expm2;

    float ecoul = pref * (fmaf(0.5f, damp, erfc) - 1.0f);                    // eV
    float fcoul = pref * (damp + erfc + EW_F * grij * expm2 - 1.0f) * inv_r; // eV/A

    float s  = fcoul * inv_r;
    float fx = dx * s;
    float fy = dy * s;
    float fz = dz * s;

    red_add_f4(&g_f4[r],  fx,  fy,  fz, ecoul);
    red_add_f4(&g_f4[c], -fx, -fy, -fz, 0.0f);
}

// -------------------- kernel 1: fused per-edge pass (4 edges/thread) --------
__global__ __launch_bounds__(128) void edge_kernel(
    const float4* __restrict__ dij4,      // [E*3/4]
    const float*  __restrict__ q,         // [N]
    const float*  __restrict__ g_ewald,   // [1] 1/m
    const int4*   __restrict__ row4,      // [E/4]
    const int4*   __restrict__ col4,      // [E/4]
    float*        __restrict__ out_energy,// [256] zeroed here (read only in finish)
    int n_chunks)
{
    // allow the dependent finish_kernel to launch & run its prologue early;
    // it gates on griddepcontrol.wait (full grid completion) before reading
    // anything this kernel writes.
    asm volatile("griddepcontrol.launch_dependents;");

    // free zeroing of the energy output: nothing reads it until finish_kernel
    if (blockIdx.x < 2) {
        out_energy[blockIdx.x * 128 + threadIdx.x] = 0.0f;
    }

    const float gA = g_ewald[0] * A2M;    // 1/Angstrom
    int j = blockIdx.x * blockDim.x + threadIdx.x;
    if (j >= n_chunks) return;

    // streaming loads: evict-first so q table keeps L1/L2 residency
    int4 r = __ldcs(&row4[j]);
    int4 c = __ldcs(&col4[j]);
    float4 d0 = __ldcs(&dij4[3 * j + 0]);
    float4 d1 = __ldcs(&dij4[3 * j + 1]);
    float4 d2 = __ldcs(&dij4[3 * j + 2]);

    do_edge(d0.x, d0.y, d0.z, r.x, c.x, q, gA);
    do_edge(d0.w, d1.x, d1.y, r.y, c.y, q, gA);
    do_edge(d1.z, d1.w, d2.x, r.z, c.z, q, gA);
    do_edge(d2.y, d2.z, d2.w, r.w, c.w, q, gA);
}

// tail handler for n_edges not divisible by 4
__global__ void edge_tail_kernel(
    const float* __restrict__ dij,
    const float* __restrict__ q,
    const float* __restrict__ g_ewald,
    const int*   __restrict__ row,
    const int*   __restrict__ col,
    int e_start, int n_edges)
{
    int i = e_start + blockIdx.x * blockDim.x + threadIdx.x;
    if (i < n_edges) {
        const float gA = g_ewald[0] * A2M;
        do_edge(dij[3 * i], dij[3 * i + 1], dij[3 * i + 2], row[i], col[i], q, gA);
    }
}

// ------------- kernel 2: unpack force + bin energy + restore scratch --------
// Launched with programmatic stream serialization: prologue (s_e zero, batch
// gather) overlaps the edge kernel's tail; griddepcontrol.wait gates the
// g_f4 reads on edge-grid completion.
__global__ __launch_bounds__(256) void finish_kernel(
    const int* __restrict__ batch,        // [N] atom -> graph (sorted)
    float*     __restrict__ out_energy,   // [256]
    float*     __restrict__ out_force,    // [N,3]
    int n_atoms)
{
    __shared__ float s_e[N_GRAPHS];
    s_e[threadIdx.x] = 0.0f;

    int a = blockIdx.x * blockDim.x + threadIdx.x;
    // prefetch batch (kernel input; not written by edge_kernel -> safe pre-wait)
    int b = (a < n_atoms) ? batch[a] : 0;
    __syncthreads();

    // wait for edge_kernel's memory (g_f4, out_energy zeros) to be visible
    asm volatile("griddepcontrol.wait;" ::: "memory");

    if (a < n_atoms) {
        float4 f = g_f4[a];
        g_f4[a] = make_float4(0.f, 0.f, 0.f, 0.f);   // restore zero invariant
        out_force[3 * a + 0] = f.x;
        out_force[3 * a + 1] = f.y;
        out_force[3 * a + 2] = f.z;

        // batch is sorted -> most warps are uniform: reduce in registers,
        // single shared atomic per warp. Boundary warps take per-lane path.
        unsigned act = __activemask();
        int b0 = __shfl_sync(act, b, 0);
        if (act == 0xFFFFFFFFu && __all_sync(act, b == b0)) {
            float v = f.w;
            v += __shfl_down_sync(act, v, 16);
            v += __shfl_down_sync(act, v, 8);
            v += __shfl_down_sync(act, v, 4);
            v += __shfl_down_sync(act, v, 2);
            v += __shfl_down_sync(act, v, 1);
            if ((threadIdx.x & 31) == 0) atomicAdd(&s_e[b0], v);
        } else {
            atomicAdd(&s_e[b], f.w);
        }
    }
    __syncthreads();

    float v = s_e[threadIdx.x];
    if (v != 0.0f) atomicAdd(&out_energy[threadIdx.x], v);
}

// -----------------------------------------------------------------------------
extern "C" void kernel_launch(void* const* d_in, const int* in_sizes, int n_in,
                              void* d_out, int out_size)
{
    const float* dij     = (const float*)d_in[0];   // [E,3]
    const float* q       = (const float*)d_in[1];   // [N]
    const float* g_ewald = (const float*)d_in[2];   // [1]
    const int*   row     = (const int*)d_in[3];     // [E]
    const int*   col     = (const int*)d_in[4];     // [E]
    const int*   batch   = (const int*)d_in[5];     // [N]

    int n_edges = in_sizes[0] / 3;
    int n_atoms = in_sizes[1];

    float* out        = (float*)d_out;
    float* out_energy = out;                 // [256]
    float* out_force  = out + N_GRAPHS;      // [N,3]

    // one 4-edge chunk per thread; 128-thread CTAs (best measured shape)
    int n_chunks = n_edges / 4;
    edge_kernel<<<(n_chunks + 127) / 128, 128>>>((const float4*)dij, q, g_ewald,
                                                 (const int4*)row, (const int4*)col,
                                                 out_energy, n_chunks);

    int tail = n_edges - n_chunks * 4;
    int finish_grid = (n_atoms + 255) / 256;

    if (tail > 0) {
        // rare path: keep plain serialization (PDL chain would gate on the
        // tail kernel, not the main edge kernel)
        edge_tail_kernel<<<1, 256>>>(dij, q, g_ewald, row, col,
                                     n_chunks * 4, n_edges);
        finish_kernel<<<finish_grid, 256>>>(batch, out_energy, out_force, n_atoms);
    } else {
        // PDL: finish launches early, prologue overlaps edge tail
        cudaLaunchConfig_t cfg = {};
        cfg.gridDim  = dim3(finish_grid, 1, 1);
        cfg.blockDim = dim3(256, 1, 1);
        cudaLaunchAttribute attrs[1];
        attrs[0].id = cudaLaunchAttributeProgrammaticStreamSerialization;
        attrs[0].val.programmaticStreamSerializationAllowed = 1;
        cfg.attrs = attrs;
        cfg.numAttrs = 1;
        cudaLaunchKernelEx(&cfg, finish_kernel, batch, out_energy, out_force, n_atoms);
    }
}